// round 9
// baseline (speedup 1.0000x reference)
#include <cuda_runtime.h>

#define NT 128
#define RPC 256                 // rows per CTA (2 per thread)
#define STEPS 15
#define SPEED 5.0f
#define NCOLS_IN 18
#define NCOLS_OUT 178
#define CB 22                   // 20 staged cols per phase + 2 pad (8B-aligned slots)
#define SMEM_BYTES (RPC * CB * 4)

template <int NC>
__device__ __forceinline__ void flush2(float* __restrict__ out,
                                       const float* __restrict__ stage,
                                       int R0, int rows_blk, int base_col, int t)
{
    constexpr int NC2 = NC / 2;          // NC even
    const unsigned total = (unsigned)rows_blk * NC2;
    for (unsigned idx = t; idx < total; idx += NT) {
        unsigned r = idx / NC2;
        unsigned k = idx - r * NC2;
        float2 v = *(const float2*)(stage + r * CB + 2 * k);
        *(float2*)(out + (long long)(R0 + r) * NCOLS_OUT + base_col + 2 * k) = v;
    }
}

__global__ void __launch_bounds__(NT) prog_kernel(
    const float* __restrict__ x,
    const float* __restrict__ c1w, const float* __restrict__ c1b,
    const float* __restrict__ c2w, const float* __restrict__ c2b,
    const float* __restrict__ l1w, const float* __restrict__ l1b,
    const float* __restrict__ l2w, const float* __restrict__ l2b,
    float* __restrict__ out, int n)
{
    extern __shared__ float s_rows[];   // RPC * CB staging

    // Pair-packed weights: 16 blocks of 20 floats (80B, 16B-aligned).
    __shared__ float s_w[16 * 20];
    __shared__ float s_cb[12];

    const int t = threadIdx.x;
    if (t < 32) {
        const int j = t;
        const int base = 20 * (j >> 1) + 10 * (j & 1);
        s_w[base + 0] = l1w[0 * 32 + j];
        s_w[base + 1] = l1w[1 * 32 + j];
        s_w[base + 2] = l1w[2 * 32 + j];
        s_w[base + 3] = l1w[3 * 32 + j];
        s_w[base + 4] = l1b[j];
        s_w[base + 5] = l2w[5 * j + 0];
        s_w[base + 6] = l2w[5 * j + 1];
        s_w[base + 7] = l2w[5 * j + 2];
        s_w[base + 8] = l2w[5 * j + 3];
        s_w[base + 9] = l2w[5 * j + 4];
    } else if (t < 64) {
        const int u = t - 32;
        if (u < 12) {
            float v;
            if      (u == 0) v = c1w[0];
            else if (u == 1) v = c1w[1];
            else if (u == 2) v = c1b[0];
            else if (u == 3) v = c2w[0];
            else if (u == 4) v = c2w[1];
            else if (u == 5) v = c2b[0];
            else if (u < 11) v = l2b[u - 6];
            else             v = 0.0f;
            s_cb[u] = v;
        }
    }
    __syncthreads();

    const int R0 = blockIdx.x * RPC;
    int rows_blk = n - R0; if (rows_blk > RPC) rows_blk = RPC;

    const float c1w0 = s_cb[0], c1w1 = s_cb[1], c1b0 = s_cb[2];
    const float c2w0 = s_cb[3], c2w1 = s_cb[4], c2b0 = s_cb[5];
    const float l2b0 = s_cb[6], l2b1 = s_cb[7], l2b2 = s_cb[8];
    const float l2b3 = s_cb[9], l2b4 = s_cb[10];

    // two rows per thread: local row ids t and t+NT
    float s0[2], s1[2], s2[2], s3[2], s4[2], s5[2], s6[2], s7[2], s8[2],
          s9[2], s10[2], s11[2], s12[2], s13[2], s14[2], s15[2], s16[2], s17[2];
    float* my[2];

    #pragma unroll
    for (int r = 0; r < 2; r++) {
        const int lr = t + r * NT;                       // local row in CTA
        const int row = R0 + ((lr < rows_blk) ? lr : 0); // clamp inactive
        my[r] = s_rows + lr * CB;
        const float* xr = x + (long long)row * NCOLS_IN;
        float2 v0 = *(const float2*)(xr + 0);
        float2 v1 = *(const float2*)(xr + 2);
        float2 v2 = *(const float2*)(xr + 4);
        float2 v3 = *(const float2*)(xr + 6);
        float2 v4 = *(const float2*)(xr + 8);
        float2 v8 = *(const float2*)(xr + 16);
        s0[r] = v0.x; s1[r] = v0.y; s2[r] = v1.x; s3[r] = v1.y;
        s4[r] = v2.x; s5[r] = v2.y; s6[r] = v3.x; s7[r] = v3.y;
        s8[r] = v4.x; s9[r] = v4.y; s17[r] = v8.y;
        float d13 = s1[r] - s3[r], d24 = s2[r] - s4[r];
        s10[r] = fmaf(d13, d13, d24 * d24);
        s11[r] = s12[r] = s13[r] = s14[r] = s15[r] = s16[r] = 0.0f;
    }

    auto stash = [&](int r, float* slot) {
        *(float2*)(slot + 0) = make_float2(s10[r], s1[r]);
        *(float2*)(slot + 2) = make_float2(s2[r], s3[r]);
        *(float2*)(slot + 4) = make_float2(s4[r], s5[r]);
        *(float2*)(slot + 6) = make_float2(s6[r], s7[r]);
        *(float2*)(slot + 8) = make_float2(s8[r], s17[r]);
    };

    auto do_step = [&](int slot_off) {
        float h20[2], h21[2], h22[2], h23[2];
        float p0[2], p1[2], p2[2], p3[2], p4[2];

        #pragma unroll
        for (int r = 0; r < 2; r++) {
            const float f0 = s1[r], f1 = s2[r], f2 = s3[r], f3 = s4[r],
                        f4 = s9[r], f5 = s17[r];
            float h10 = fmaxf(fmaf(c1w1, f1, fmaf(c1w0, f0, c1b0)), 0.0f);
            float h11 = fmaxf(fmaf(c1w1, f2, fmaf(c1w0, f1, c1b0)), 0.0f);
            float h12 = fmaxf(fmaf(c1w1, f3, fmaf(c1w0, f2, c1b0)), 0.0f);
            float h13 = fmaxf(fmaf(c1w1, f4, fmaf(c1w0, f3, c1b0)), 0.0f);
            float h14 = fmaxf(fmaf(c1w1, f5, fmaf(c1w0, f4, c1b0)), 0.0f);
            h20[r] = fmaxf(fmaf(c2w1, h11, fmaf(c2w0, h10, c2b0)), 0.0f);
            h21[r] = fmaxf(fmaf(c2w1, h12, fmaf(c2w0, h11, c2b0)), 0.0f);
            h22[r] = fmaxf(fmaf(c2w1, h13, fmaf(c2w0, h12, c2b0)), 0.0f);
            h23[r] = fmaxf(fmaf(c2w1, h14, fmaf(c2w0, h13, c2b0)), 0.0f);
            p0[r] = l2b0; p1[r] = l2b1; p2[r] = l2b2; p3[r] = l2b3; p4[r] = l2b4;
        }

        #pragma unroll 8
        for (int q = 0; q < 16; q++) {
            const float4 a0 = *(const float4*)(s_w + 20 * q + 0);
            const float4 a1 = *(const float4*)(s_w + 20 * q + 4);
            const float4 a2 = *(const float4*)(s_w + 20 * q + 8);
            const float4 a3 = *(const float4*)(s_w + 20 * q + 12);
            const float4 a4 = *(const float4*)(s_w + 20 * q + 16);

            #pragma unroll
            for (int r = 0; r < 2; r++) {
                float h3a = fmaf(h23[r], a0.w,
                            fmaf(h22[r], a0.z,
                            fmaf(h21[r], a0.y,
                            fmaf(h20[r], a0.x, a1.x))));
                h3a = fmaxf(h3a, 0.0f);
                p0[r] = fmaf(h3a, a1.y, p0[r]);
                p1[r] = fmaf(h3a, a1.z, p1[r]);
                p2[r] = fmaf(h3a, a1.w, p2[r]);
                p3[r] = fmaf(h3a, a2.x, p3[r]);
                p4[r] = fmaf(h3a, a2.y, p4[r]);

                float h3b = fmaf(h23[r], a3.y,
                            fmaf(h22[r], a3.x,
                            fmaf(h21[r], a2.w,
                            fmaf(h20[r], a2.z, a3.z))));
                h3b = fmaxf(h3b, 0.0f);
                p0[r] = fmaf(h3b, a3.w, p0[r]);
                p1[r] = fmaf(h3b, a4.x, p1[r]);
                p2[r] = fmaf(h3b, a4.y, p2[r]);
                p3[r] = fmaf(h3b, a4.z, p3[r]);
                p4[r] = fmaf(h3b, a4.w, p4[r]);
            }
        }

        #pragma unroll
        for (int r = 0; r < 2; r++) {
            float q0 = 1.0f / (1.0f + expf(-p0[r]));
            float q1 = 1.0f / (1.0f + expf(-p1[r]));
            float q2 = 1.0f / (1.0f + expf(-p2[r]));
            float q3 = 1.0f / (1.0f + expf(-p3[r]));
            float q4 = 1.0f / (1.0f + expf(-p4[r]));

            s5[r] = q0; s6[r] = q1; s7[r] = q2; s8[r] = q3; s17[r] = q4;

            const float a = q1 - q0, b = q2 - q0, c = q3 - q0;
            const float d = q2 - q1, e = q3 - q1, f = q3 - q2;
            s11[r] = a; s12[r] = b; s13[r] = c;
            s14[r] = d; s15[r] = e; s16[r] = f;

            const float dx_c = (c <= 0.0f) ? 0.0f : SPEED;
            const float st_c = (c <= 0.0f) ? 0.0f : 3.0f;
            const float dx_f = (f <= 0.0f) ? 0.0f : SPEED;
            const float st_f = (f <= 0.0f) ? 2.0f : 3.0f;
            const float dx_e = (e <= 0.0f) ? -SPEED : SPEED;
            const float st_e = (e <= 0.0f) ? 1.0f : 3.0f;
            const float dx_b = (b <= 0.0f) ? dx_c : dx_f;
            const float st_b = (b <= 0.0f) ? st_c : st_f;
            const float dx_d = (d <= 0.0f) ? dx_e : dx_f;
            const float st_d = (d <= 0.0f) ? st_e : st_f;
            const float dx   = (a <= 0.0f) ? dx_b : dx_d;
            const float st   = (a <= 0.0f) ? st_b : st_d;

            s1[r] += dx;
            s9[r] = st;
            s2[r] += SPEED;
            s3[r] += SPEED;
            s0[r] += 1.0f;
            float d13 = s1[r] - s3[r], d24 = s2[r] - s4[r];
            s10[r] = fmaf(d13, d13, d24 * d24);

            stash(r, my[r] + slot_off);
        }
    };

    // Phase A: traj0 (slots 0..9) + step 0 (slots 10..19) -> cols 18..37
    #pragma unroll
    for (int r = 0; r < 2; r++) stash(r, my[r]);
    do_step(10);
    __syncthreads();
    flush2<20>(out, s_rows, R0, rows_blk, 18, t);
    __syncthreads();

    // Phases B..H: steps (1,2),(3,4),...,(13,14) -> 20 cols each
    #pragma unroll 1
    for (int ph = 0; ph < 7; ph++) {
        do_step(0);
        do_step(10);
        __syncthreads();
        flush2<20>(out, s_rows, R0, rows_blk, 38 + 20 * ph, t);
        __syncthreads();
    }

    // Phase I: final state (18 cols) -> cols 0..17
    #pragma unroll
    for (int r = 0; r < 2; r++) {
        float* m = my[r];
        *(float2*)(m + 0)  = make_float2(s0[r], s1[r]);
        *(float2*)(m + 2)  = make_float2(s2[r], s3[r]);
        *(float2*)(m + 4)  = make_float2(s4[r], s5[r]);
        *(float2*)(m + 6)  = make_float2(s6[r], s7[r]);
        *(float2*)(m + 8)  = make_float2(s8[r], s9[r]);
        *(float2*)(m + 10) = make_float2(s10[r], s11[r]);
        *(float2*)(m + 12) = make_float2(s12[r], s13[r]);
        *(float2*)(m + 14) = make_float2(s14[r], s15[r]);
        *(float2*)(m + 16) = make_float2(s16[r], s17[r]);
    }
    __syncthreads();
    flush2<18>(out, s_rows, R0, rows_blk, 0, t);
}

extern "C" void kernel_launch(void* const* d_in, const int* in_sizes, int n_in,
                              void* d_out, int out_size)
{
    const float* x   = (const float*)d_in[0];
    const float* c1w = (const float*)d_in[1];
    const float* c1b = (const float*)d_in[2];
    const float* c2w = (const float*)d_in[3];
    const float* c2b = (const float*)d_in[4];
    const float* l1w = (const float*)d_in[5];
    const float* l1b = (const float*)d_in[6];
    const float* l2w = (const float*)d_in[7];
    const float* l2b = (const float*)d_in[8];
    float* out = (float*)d_out;

    const int n = in_sizes[0] / NCOLS_IN;
    const int blocks = (n + RPC - 1) / RPC;
    prog_kernel<<<blocks, NT, SMEM_BYTES>>>(x, c1w, c1b, c2w, c2b,
                                            l1w, l1b, l2w, l2b, out, n);
}